// round 2
// baseline (speedup 1.0000x reference)
#include <cuda_runtime.h>

// Problem constants (fixed by setup_inputs; deterministic)
#define NB    2
#define NTT   2
#define NLG   256
#define TT    64
#define SS    256
#define NVV   4
#define FF    16
#define KNN   3
#define CUTOFF   1e-3f
#define MASKVAL  1e6f

#define DROW  260   // padded row stride for dist tile (floats)
#define PROW  264   // padded row stride for penalty table (floats)
#define SMEM_FLOATS (TT*DROW + NVV*PROW)
#define SMEM_BYTES  (SMEM_FLOATS * 4)

__device__ __forceinline__ void top3_insert(float v, int s,
                                            float& d0, float& d1, float& d2,
                                            int& i0, int& i1, int& i2) {
    // strict < : on ties the earlier (smaller) index stays ranked first,
    // matching jax.lax.top_k stability.
    if (v < d2) {
        if (v < d1) {
            d2 = d1; i2 = i1;
            if (v < d0) { d1 = d0; i1 = i0; d0 = v; i0 = s; }
            else        { d1 = v;  i1 = s; }
        } else {
            d2 = v; i2 = s;
        }
    }
}

__global__ __launch_bounds__(256) void interp_kernel(
    const float* __restrict__ x,            // (B,NT, NL*S, NV, F)
    const void*  __restrict__ mask_raw,     // (B,NT, NL*S, NV) — dtype detected
    const float* __restrict__ dist,         // (B, NL, T, S)
    float* __restrict__ out)
{
    extern __shared__ float sm[];
    float* sd = sm;                // [TT][DROW] dist tile
    float* sp = sm + TT * DROW;    // [NVV][PROW] penalty (transposed)
    __shared__ int s_flags[2];     // [0]: uint8 evidence, [1]: float32 evidence

    const int bid = blockIdx.x;
    const int l   = bid & 255;
    const int nt  = (bid >> 8) & 1;
    const int b   = bid >> 9;
    const int tid = threadIdx.x;

    if (tid == 0) { s_flags[0] = 0; s_flags[1] = 0; }
    __syncthreads();

    // ---- mask dtype detection from first 1024 bytes (valid under all layouts) ----
    {
        const uchar4* mb = (const uchar4*)mask_raw;
        uchar4 q = mb[tid];                         // bytes 4*tid .. 4*tid+3
        // uint8 bool: a value of 1 at a position not divisible by 4
        int u8  = (q.y == 1) | (q.z == 1) | (q.w == 1);
        // float32 1.0f = bytes 00 00 80 3F -> 0x3F present somewhere
        int f32 = (q.x == 0x3F) | (q.y == 0x3F) | (q.z == 0x3F) | (q.w == 0x3F);
        if (u8)  atomicOr(&s_flags[0], 1);
        if (f32) atomicOr(&s_flags[1], 1);
    }

    // ---- stage dist tile: contiguous 64*256 floats for (b,l) ----
    {
        const float4* dsrc = (const float4*)(dist + ((size_t)(b * NLG + l)) * TT * SS);
        #pragma unroll
        for (int k = 0; k < 16; k++) {
            int g = tid + k * 256;
            float4 v = dsrc[g];
            int flat = g * 4;
            int t = flat >> 8;
            int s = flat & 255;
            *(float4*)&sd[t * DROW + s] = v;
        }
    }
    __syncthreads();
    const int mkind = s_flags[0] ? 0 : (s_flags[1] ? 2 : 1);

    // ---- stage mask -> penalty table, transposed [nv][s] ----
    {
        const size_t moff = ((size_t)((b * NTT + nt) * NLG + l)) * SS * NVV; // elements
        if (mkind == 0) {            // uint8
            const uchar4* msrc = (const uchar4*)((const unsigned char*)mask_raw + moff);
            uchar4 m = msrc[tid];    // s = tid, nv = 0..3
            sp[0 * PROW + tid] = m.x ? MASKVAL : 0.0f;
            sp[1 * PROW + tid] = m.y ? MASKVAL : 0.0f;
            sp[2 * PROW + tid] = m.z ? MASKVAL : 0.0f;
            sp[3 * PROW + tid] = m.w ? MASKVAL : 0.0f;
        } else if (mkind == 1) {     // int32
            const int4* msrc = (const int4*)((const int*)mask_raw + moff);
            int4 m = msrc[tid];
            sp[0 * PROW + tid] = m.x ? MASKVAL : 0.0f;
            sp[1 * PROW + tid] = m.y ? MASKVAL : 0.0f;
            sp[2 * PROW + tid] = m.z ? MASKVAL : 0.0f;
            sp[3 * PROW + tid] = m.w ? MASKVAL : 0.0f;
        } else {                     // float32 (0.0f / 1.0f)
            const float4* msrc = (const float4*)((const float*)mask_raw + moff);
            float4 m = msrc[tid];
            sp[0 * PROW + tid] = m.x * MASKVAL;
            sp[1 * PROW + tid] = m.y * MASKVAL;
            sp[2 * PROW + tid] = m.z * MASKVAL;
            sp[3 * PROW + tid] = m.w * MASKVAL;
        }
    }
    __syncthreads();

    const int t  = tid >> 2;
    const int nv = tid & 3;
    const float* drow = &sd[t * DROW];
    const float* prow = &sp[nv * PROW];

    float d0 = 3.4e38f, d1 = 3.4e38f, d2 = 3.4e38f;
    int   i0 = 0, i1 = 0, i2 = 0;

    #pragma unroll 8
    for (int k = 0; k < SS / 4; k++) {
        float4 dv = *(const float4*)(drow + k * 4);
        float4 pv = *(const float4*)(prow + k * 4);
        int s = k * 4;
        top3_insert(dv.x + pv.x, s + 0, d0, d1, d2, i0, i1, i2);
        top3_insert(dv.y + pv.y, s + 1, d0, d1, d2, i0, i1, i2);
        top3_insert(dv.z + pv.z, s + 2, d0, d1, d2, i0, i1, i2);
        top3_insert(dv.w + pv.w, s + 3, d0, d1, d2, i0, i1, i2);
    }

    // ---- weights ----
    float c0 = fmaxf(d0, CUTOFF);
    float c1 = fmaxf(d1, CUTOFF);
    float c2 = fmaxf(d2, CUTOFF);
    float w0 = 1.0f / (c0 * c0);
    float w1 = 1.0f / (c1 * c1);
    float w2 = 1.0f / (c2 * c2);
    float inv = 1.0f / (w0 + w1 + w2);
    w0 *= inv; w1 *= inv; w2 *= inv;

    // ---- gather + blend (3 neighbors x 16 floats, as float4) ----
    const float* xb = x + ((size_t)((b * NTT + nt) * NLG + l)) * SS * NVV * FF;
    const float4* p0 = (const float4*)(xb + ((size_t)i0 * NVV + nv) * FF);
    const float4* p1 = (const float4*)(xb + ((size_t)i1 * NVV + nv) * FF);
    const float4* p2 = (const float4*)(xb + ((size_t)i2 * NVV + nv) * FF);

    const size_t row = (size_t)((b * NTT + nt) * (NLG * TT)) + (size_t)l * TT + t;
    float4* op = (float4*)(out + (row * NVV + nv) * FF);

    #pragma unroll
    for (int j = 0; j < 4; j++) {
        float4 a = p0[j], bb = p1[j], cc = p2[j];
        float4 r;
        r.x = w0 * a.x + w1 * bb.x + w2 * cc.x;
        r.y = w0 * a.y + w1 * bb.y + w2 * cc.y;
        r.z = w0 * a.z + w1 * bb.z + w2 * cc.z;
        r.w = w0 * a.w + w1 * bb.w + w2 * cc.w;
        op[j] = r;
    }

    // ---- dist_vals output (clamped), after x_inter block ----
    const size_t XSZ = (size_t)NB * NTT * NLG * TT * NVV * FF;  // 4,194,304
    size_t dbase = XSZ + (row * KNN) * NVV + nv;
    out[dbase]            = c0;
    out[dbase + NVV]      = c1;
    out[dbase + 2 * NVV]  = c2;
}

extern "C" void kernel_launch(void* const* d_in, const int* in_sizes, int n_in,
                              void* d_out, int out_size) {
    const float* x    = (const float*)d_in[0];
    const void*  mask = (const void*)d_in[1];
    const float* dist = (const float*)d_in[2];
    float*       out  = (float*)d_out;

    cudaFuncSetAttribute(interp_kernel,
                         cudaFuncAttributeMaxDynamicSharedMemorySize, SMEM_BYTES);
    interp_kernel<<<NB * NTT * NLG, 256, SMEM_BYTES>>>(x, mask, dist, out);
}

// round 3
// speedup vs baseline: 1.1476x; 1.1476x over previous
#include <cuda_runtime.h>

#define NB    2
#define NTT   2
#define NLG   256
#define TT    64
#define SS    256
#define NVV   4
#define FF    16
#define KNN   3
#define CUTOFF   1e-3f
#define MASKVAL  1e6f

#define PROW  260   // padded row stride for penalty table (floats)
#define SMEM_FLOATS (NVV*PROW)
#define SMEM_BYTES  (SMEM_FLOATS * 4)

#define BIGV 3.4e38f
#define BIGI 0x3fffffff

// plain strict-< insert: stable when indices ascend during the scan
__device__ __forceinline__ void top3_insert(float v, int s,
                                            float& d0, float& d1, float& d2,
                                            int& i0, int& i1, int& i2) {
    if (v < d2) {
        if (v < d1) {
            d2 = d1; i2 = i1;
            if (v < d0) { d1 = d0; i1 = i0; d0 = v; i0 = s; }
            else        { d1 = v;  i1 = s; }
        } else {
            d2 = v; i2 = s;
        }
    }
}

__device__ __forceinline__ bool lessvi(float v, int i, float w, int j) {
    return (v < w) || (v == w && i < j);
}

// lexicographic (value, index) insert for cross-partition merge
__device__ __forceinline__ void top3_insert_vi(float v, int s,
                                               float& d0, float& d1, float& d2,
                                               int& i0, int& i1, int& i2) {
    if (lessvi(v, s, d2, i2)) {
        if (lessvi(v, s, d1, i1)) {
            d2 = d1; i2 = i1;
            if (lessvi(v, s, d0, i0)) { d1 = d0; i1 = i0; d0 = v; i0 = s; }
            else                      { d1 = v;  i1 = s; }
        } else {
            d2 = v; i2 = s;
        }
    }
}

__global__ __launch_bounds__(256) void interp_kernel(
    const float* __restrict__ x,            // (B,NT, NL*S, NV, F)
    const void*  __restrict__ mask_raw,     // (B,NT, NL*S, NV) — dtype detected
    const float* __restrict__ dist,         // (B, NL, T, S)
    float* __restrict__ out)
{
    __shared__ float sp[SMEM_FLOATS];       // [NVV][PROW] penalty (transposed)
    __shared__ int s_flags[2];

    const int bid = blockIdx.x;
    const int l   = bid & 255;
    const int nt  = (bid >> 8) & 1;
    const int b   = bid >> 9;
    const int tid = threadIdx.x;

    if (tid == 0) { s_flags[0] = 0; s_flags[1] = 0; }
    __syncthreads();

    // ---- mask dtype detection from first 1024 bytes ----
    {
        const uchar4* mb = (const uchar4*)mask_raw;
        uchar4 q = mb[tid];
        int u8  = (q.y == 1) | (q.z == 1) | (q.w == 1);
        int f32 = (q.x == 0x3F) | (q.y == 0x3F) | (q.z == 0x3F) | (q.w == 0x3F);
        if (u8)  atomicOr(&s_flags[0], 1);
        if (f32) atomicOr(&s_flags[1], 1);
    }
    __syncthreads();
    const int mkind = s_flags[0] ? 0 : (s_flags[1] ? 2 : 1);

    // ---- stage mask -> penalty table, transposed [nv][s] ----
    {
        const size_t moff = ((size_t)((b * NTT + nt) * NLG + l)) * SS * NVV;
        if (mkind == 0) {            // uint8
            const uchar4* msrc = (const uchar4*)((const unsigned char*)mask_raw + moff);
            uchar4 m = msrc[tid];
            sp[0 * PROW + tid] = m.x ? MASKVAL : 0.0f;
            sp[1 * PROW + tid] = m.y ? MASKVAL : 0.0f;
            sp[2 * PROW + tid] = m.z ? MASKVAL : 0.0f;
            sp[3 * PROW + tid] = m.w ? MASKVAL : 0.0f;
        } else if (mkind == 1) {     // int32
            const int4* msrc = (const int4*)((const int*)mask_raw + moff);
            int4 m = msrc[tid];
            sp[0 * PROW + tid] = m.x ? MASKVAL : 0.0f;
            sp[1 * PROW + tid] = m.y ? MASKVAL : 0.0f;
            sp[2 * PROW + tid] = m.z ? MASKVAL : 0.0f;
            sp[3 * PROW + tid] = m.w ? MASKVAL : 0.0f;
        } else {                     // float32 0/1
            const float4* msrc = (const float4*)((const float*)mask_raw + moff);
            float4 m = msrc[tid];
            sp[0 * PROW + tid] = m.x * MASKVAL;
            sp[1 * PROW + tid] = m.y * MASKVAL;
            sp[2 * PROW + tid] = m.z * MASKVAL;
            sp[3 * PROW + tid] = m.w * MASKVAL;
        }
    }
    __syncthreads();

    const int t  = tid >> 2;
    const int nv = tid & 3;
    const float4* drow =
        (const float4*)(dist + (((size_t)(b * NLG + l)) * TT + t) * SS);
    const float* prow = &sp[nv * PROW];

    // 4 independent top-3 accumulators (partition p = s % 4) -> 4x ILP
    float a0 = BIGV, a1 = BIGV, a2 = BIGV;  int ai0 = BIGI, ai1 = BIGI, ai2 = BIGI;
    float b0 = BIGV, b1 = BIGV, b2 = BIGV;  int bi0 = BIGI, bi1 = BIGI, bi2 = BIGI;
    float c0 = BIGV, c1 = BIGV, c2 = BIGV;  int ci0 = BIGI, ci1 = BIGI, ci2 = BIGI;
    float e0 = BIGV, e1 = BIGV, e2 = BIGV;  int ei0 = BIGI, ei1 = BIGI, ei2 = BIGI;

    #pragma unroll 8
    for (int k = 0; k < SS / 4; k++) {
        float4 dv = __ldg(&drow[k]);
        float4 pv = *(const float4*)(prow + k * 4);
        int s = k * 4;
        top3_insert(dv.x + pv.x, s + 0, a0, a1, a2, ai0, ai1, ai2);
        top3_insert(dv.y + pv.y, s + 1, b0, b1, b2, bi0, bi1, bi2);
        top3_insert(dv.z + pv.z, s + 2, c0, c1, c2, ci0, ci1, ci2);
        top3_insert(dv.w + pv.w, s + 3, e0, e1, e2, ei0, ei1, ei2);
    }

    // merge partitions 1..3 into partition 0 (lexicographic, ascending order)
    top3_insert_vi(b0, bi0, a0, a1, a2, ai0, ai1, ai2);
    top3_insert_vi(b1, bi1, a0, a1, a2, ai0, ai1, ai2);
    top3_insert_vi(b2, bi2, a0, a1, a2, ai0, ai1, ai2);
    top3_insert_vi(c0, ci0, a0, a1, a2, ai0, ai1, ai2);
    top3_insert_vi(c1, ci1, a0, a1, a2, ai0, ai1, ai2);
    top3_insert_vi(c2, ci2, a0, a1, a2, ai0, ai1, ai2);
    top3_insert_vi(e0, ei0, a0, a1, a2, ai0, ai1, ai2);
    top3_insert_vi(e1, ei1, a0, a1, a2, ai0, ai1, ai2);
    top3_insert_vi(e2, ei2, a0, a1, a2, ai0, ai1, ai2);

    // ---- weights ----
    float q0 = fmaxf(a0, CUTOFF);
    float q1 = fmaxf(a1, CUTOFF);
    float q2 = fmaxf(a2, CUTOFF);
    float w0 = 1.0f / (q0 * q0);
    float w1 = 1.0f / (q1 * q1);
    float w2 = 1.0f / (q2 * q2);
    float inv = 1.0f / (w0 + w1 + w2);
    w0 *= inv; w1 *= inv; w2 *= inv;

    // ---- gather + blend ----
    const float* xb = x + ((size_t)((b * NTT + nt) * NLG + l)) * SS * NVV * FF;
    const float4* p0 = (const float4*)(xb + ((size_t)ai0 * NVV + nv) * FF);
    const float4* p1 = (const float4*)(xb + ((size_t)ai1 * NVV + nv) * FF);
    const float4* p2 = (const float4*)(xb + ((size_t)ai2 * NVV + nv) * FF);

    const size_t row = (size_t)((b * NTT + nt) * (NLG * TT)) + (size_t)l * TT + t;
    float4* op = (float4*)(out + (row * NVV + nv) * FF);

    #pragma unroll
    for (int j = 0; j < 4; j++) {
        float4 va = p0[j], vb = p1[j], vc = p2[j];
        float4 r;
        r.x = w0 * va.x + w1 * vb.x + w2 * vc.x;
        r.y = w0 * va.y + w1 * vb.y + w2 * vc.y;
        r.z = w0 * va.z + w1 * vb.z + w2 * vc.z;
        r.w = w0 * va.w + w1 * vb.w + w2 * vc.w;
        op[j] = r;
    }

    // ---- dist_vals output ----
    const size_t XSZ = (size_t)NB * NTT * NLG * TT * NVV * FF;  // 4,194,304
    size_t dbase = XSZ + (row * KNN) * NVV + nv;
    out[dbase]           = q0;
    out[dbase + NVV]     = q1;
    out[dbase + 2 * NVV] = q2;
}

extern "C" void kernel_launch(void* const* d_in, const int* in_sizes, int n_in,
                              void* d_out, int out_size) {
    const float* x    = (const float*)d_in[0];
    const void*  mask = (const void*)d_in[1];
    const float* dist = (const float*)d_in[2];
    float*       out  = (float*)d_out;

    interp_kernel<<<NB * NTT * NLG, 256>>>(x, mask, dist, out);
}

// round 4
// speedup vs baseline: 1.1914x; 1.0382x over previous
#include <cuda_runtime.h>
#include <cstdint>

#define NB    2
#define NTT   2
#define NLG   256
#define TT    64
#define SS    256
#define NVV   4
#define FF    16
#define KNN   3
#define CUTOFF   1e-3f
#define MASKVAL  1e6f

#define PROW  260   // padded row stride for penalty table (floats)
#define SMEM_FLOATS (NVV*PROW)

#define BIGV 3.4e38f
#define BIGI 0x3fffffff

// plain strict-< insert: stable while indices ascend during the scan
__device__ __forceinline__ void top3_insert(float v, int s,
                                            float& d0, float& d1, float& d2,
                                            int& i0, int& i1, int& i2) {
    if (v < d2) {
        if (v < d1) {
            d2 = d1; i2 = i1;
            if (v < d0) { d1 = d0; i1 = i0; d0 = v; i0 = s; }
            else        { d1 = v;  i1 = s; }
        } else {
            d2 = v; i2 = s;
        }
    }
}

__device__ __forceinline__ bool lessvi(float v, int i, float w, int j) {
    return (v < w) || (v == w && i < j);
}

// lexicographic (value, index) insert for merges
__device__ __forceinline__ void top3_insert_vi(float v, int s,
                                               float& d0, float& d1, float& d2,
                                               int& i0, int& i1, int& i2) {
    if (lessvi(v, s, d2, i2)) {
        if (lessvi(v, s, d1, i1)) {
            d2 = d1; i2 = i1;
            if (lessvi(v, s, d0, i0)) { d1 = d0; i1 = i0; d0 = v; i0 = s; }
            else                      { d1 = v;  i1 = s; }
        } else {
            d2 = v; i2 = s;
        }
    }
}

// packed f32x2 add (Blackwell)
__device__ __forceinline__ void add2(float& rx, float& ry,
                                     float ax, float ay, float bx, float by) {
    uint64_t a, b, r;
    asm("mov.b64 %0, {%1, %2};" : "=l"(a) : "f"(ax), "f"(ay));
    asm("mov.b64 %0, {%1, %2};" : "=l"(b) : "f"(bx), "f"(by));
    asm("add.rn.f32x2 %0, %1, %2;" : "=l"(r) : "l"(a), "l"(b));
    asm("mov.b64 {%0, %1}, %2;" : "=f"(rx), "=f"(ry) : "l"(r));
}

__global__ __launch_bounds__(256, 5) void interp_kernel(
    const float* __restrict__ x,            // (B,NT, NL*S, NV, F)
    const void*  __restrict__ mask_raw,     // (B,NT, NL*S, NV) — dtype detected
    const float* __restrict__ dist,         // (B, NL, T, S)
    float* __restrict__ out)
{
    __shared__ float sp[SMEM_FLOATS];       // [NVV][PROW] penalty (transposed)
    __shared__ int s_flags[2];

    const int bid   = blockIdx.x;
    const int tb    = bid & 1;               // which half of the 64 targets
    const int group = bid >> 1;
    const int l     = group & 255;
    const int nt    = (group >> 8) & 1;
    const int b     = group >> 9;
    const int tid   = threadIdx.x;

    if (tid == 0) { s_flags[0] = 0; s_flags[1] = 0; }
    __syncthreads();

    // ---- mask dtype detection from first 1024 bytes ----
    {
        const uchar4* mb = (const uchar4*)mask_raw;
        uchar4 q = mb[tid];
        int u8  = (q.y == 1) | (q.z == 1) | (q.w == 1);
        int f32 = (q.x == 0x3F) | (q.y == 0x3F) | (q.z == 0x3F) | (q.w == 0x3F);
        if (u8)  atomicOr(&s_flags[0], 1);
        if (f32) atomicOr(&s_flags[1], 1);
    }
    __syncthreads();
    const int mkind = s_flags[0] ? 0 : (s_flags[1] ? 2 : 1);

    // ---- stage mask -> penalty table, transposed [nv][s] (tid = s) ----
    {
        const size_t moff = ((size_t)((b * NTT + nt) * NLG + l)) * SS * NVV;
        if (mkind == 0) {            // uint8
            const uchar4* msrc = (const uchar4*)((const unsigned char*)mask_raw + moff);
            uchar4 m = msrc[tid];
            sp[0 * PROW + tid] = m.x ? MASKVAL : 0.0f;
            sp[1 * PROW + tid] = m.y ? MASKVAL : 0.0f;
            sp[2 * PROW + tid] = m.z ? MASKVAL : 0.0f;
            sp[3 * PROW + tid] = m.w ? MASKVAL : 0.0f;
        } else if (mkind == 1) {     // int32
            const int4* msrc = (const int4*)((const int*)mask_raw + moff);
            int4 m = msrc[tid];
            sp[0 * PROW + tid] = m.x ? MASKVAL : 0.0f;
            sp[1 * PROW + tid] = m.y ? MASKVAL : 0.0f;
            sp[2 * PROW + tid] = m.z ? MASKVAL : 0.0f;
            sp[3 * PROW + tid] = m.w ? MASKVAL : 0.0f;
        } else {                     // float32 0/1
            const float4* msrc = (const float4*)((const float*)mask_raw + moff);
            float4 m = msrc[tid];
            sp[0 * PROW + tid] = m.x * MASKVAL;
            sp[1 * PROW + tid] = m.y * MASKVAL;
            sp[2 * PROW + tid] = m.z * MASKVAL;
            sp[3 * PROW + tid] = m.w * MASKVAL;
        }
    }
    __syncthreads();

    // thread decomposition: nv = tid&3, h = (tid>>2)&1 (s-half), t = tid>>3
    const int nv = tid & 3;
    const int h  = (tid >> 2) & 1;
    const int t  = (tid >> 3) + tb * 32;    // global target 0..63

    const int sbase = h * 128;               // this thread's s-range start
    const float4* drow =
        (const float4*)(dist + (((size_t)(b * NLG + l)) * TT + t) * SS + sbase);
    const float* prow = &sp[nv * PROW + sbase];

    // 4 independent top-3 accumulators (partition p = s % 4)
    float a0 = BIGV, a1 = BIGV, a2 = BIGV;  int ai0 = BIGI, ai1 = BIGI, ai2 = BIGI;
    float b0 = BIGV, b1 = BIGV, b2 = BIGV;  int bi0 = BIGI, bi1 = BIGI, bi2 = BIGI;
    float c0 = BIGV, c1 = BIGV, c2 = BIGV;  int ci0 = BIGI, ci1 = BIGI, ci2 = BIGI;
    float e0 = BIGV, e1 = BIGV, e2 = BIGV;  int ei0 = BIGI, ei1 = BIGI, ei2 = BIGI;

    #pragma unroll 8
    for (int k = 0; k < 32; k++) {
        float4 dv = __ldg(&drow[k]);
        float4 pv = *(const float4*)(prow + k * 4);
        float vx, vy, vz, vw;
        add2(vx, vy, dv.x, dv.y, pv.x, pv.y);
        add2(vz, vw, dv.z, dv.w, pv.z, pv.w);
        int s = sbase + k * 4;
        top3_insert(vx, s + 0, a0, a1, a2, ai0, ai1, ai2);
        top3_insert(vy, s + 1, b0, b1, b2, bi0, bi1, bi2);
        top3_insert(vz, s + 2, c0, c1, c2, ci0, ci1, ci2);
        top3_insert(vw, s + 3, e0, e1, e2, ei0, ei1, ei2);
    }

    // merge partitions 1..3 into partition 0 (lexicographic)
    top3_insert_vi(b0, bi0, a0, a1, a2, ai0, ai1, ai2);
    top3_insert_vi(b1, bi1, a0, a1, a2, ai0, ai1, ai2);
    top3_insert_vi(b2, bi2, a0, a1, a2, ai0, ai1, ai2);
    top3_insert_vi(c0, ci0, a0, a1, a2, ai0, ai1, ai2);
    top3_insert_vi(c1, ci1, a0, a1, a2, ai0, ai1, ai2);
    top3_insert_vi(c2, ci2, a0, a1, a2, ai0, ai1, ai2);
    top3_insert_vi(e0, ei0, a0, a1, a2, ai0, ai1, ai2);
    top3_insert_vi(e1, ei1, a0, a1, a2, ai0, ai1, ai2);
    top3_insert_vi(e2, ei2, a0, a1, a2, ai0, ai1, ai2);

    // merge the two s-halves via shuffle (partner = lane ^ 4); both sides
    // compute the identical merged result.
    {
        float ov0 = __shfl_xor_sync(0xffffffffu, a0, 4);
        float ov1 = __shfl_xor_sync(0xffffffffu, a1, 4);
        float ov2 = __shfl_xor_sync(0xffffffffu, a2, 4);
        int   oi0 = __shfl_xor_sync(0xffffffffu, ai0, 4);
        int   oi1 = __shfl_xor_sync(0xffffffffu, ai1, 4);
        int   oi2 = __shfl_xor_sync(0xffffffffu, ai2, 4);
        top3_insert_vi(ov0, oi0, a0, a1, a2, ai0, ai1, ai2);
        top3_insert_vi(ov1, oi1, a0, a1, a2, ai0, ai1, ai2);
        top3_insert_vi(ov2, oi2, a0, a1, a2, ai0, ai1, ai2);
    }

    // ---- weights ----
    float q0 = fmaxf(a0, CUTOFF);
    float q1 = fmaxf(a1, CUTOFF);
    float q2 = fmaxf(a2, CUTOFF);
    float w0 = 1.0f / (q0 * q0);
    float w1 = 1.0f / (q1 * q1);
    float w2 = 1.0f / (q2 * q2);
    float inv = 1.0f / (w0 + w1 + w2);
    w0 *= inv; w1 *= inv; w2 *= inv;

    // ---- gather + blend: each half-thread writes 2 of the 4 float4s ----
    const float* xb = x + ((size_t)((b * NTT + nt) * NLG + l)) * SS * NVV * FF;
    const float4* p0 = (const float4*)(xb + ((size_t)ai0 * NVV + nv) * FF);
    const float4* p1 = (const float4*)(xb + ((size_t)ai1 * NVV + nv) * FF);
    const float4* p2 = (const float4*)(xb + ((size_t)ai2 * NVV + nv) * FF);

    const size_t row = (size_t)((b * NTT + nt) * (NLG * TT)) + (size_t)l * TT + t;
    float4* op = (float4*)(out + (row * NVV + nv) * FF);

    const int j0 = h * 2;
    #pragma unroll
    for (int j = j0; j < j0 + 2; j++) {
        float4 va = p0[j], vb = p1[j], vc = p2[j];
        float4 r;
        r.x = w0 * va.x + w1 * vb.x + w2 * vc.x;
        r.y = w0 * va.y + w1 * vb.y + w2 * vc.y;
        r.z = w0 * va.z + w1 * vb.z + w2 * vc.z;
        r.w = w0 * va.w + w1 * vb.w + w2 * vc.w;
        op[j] = r;
    }

    // ---- dist_vals output: split between the two half-threads ----
    const size_t XSZ = (size_t)NB * NTT * NLG * TT * NVV * FF;  // 4,194,304
    size_t dbase = XSZ + (row * KNN) * NVV + nv;
    if (h == 0) {
        out[dbase]       = q0;
        out[dbase + NVV] = q1;
    } else {
        out[dbase + 2 * NVV] = q2;
    }
}

extern "C" void kernel_launch(void* const* d_in, const int* in_sizes, int n_in,
                              void* d_out, int out_size) {
    const float* x    = (const float*)d_in[0];
    const void*  mask = (const void*)d_in[1];
    const float* dist = (const float*)d_in[2];
    float*       out  = (float*)d_out;

    interp_kernel<<<NB * NTT * NLG * 2, 256>>>(x, mask, dist, out);
}

// round 5
// speedup vs baseline: 1.2740x; 1.0693x over previous
#include <cuda_runtime.h>
#include <cstdint>

#define NB    2
#define NTT   2
#define NLG   256
#define TT    64
#define SS    256
#define NVV   4
#define FF    16
#define KNN   3
#define CUTOFF   1e-3f
#define MASKVAL  1e6f

// conflict-engineered SMEM layouts:
// dist tile: [t_local(32)][h(2)][132]  row stride 264 (t -> +8 banks, h -> +4 banks)
// penalty:   [nv(4)][h(2)][132]        row stride 264
#define HROW  132
#define ROWST 264
#define DIST_FLOATS (32 * ROWST)           // 8448
#define PEN_OFF     DIST_FLOATS
#define SMEM_FLOATS (DIST_FLOATS + NVV * ROWST)  // 9504 floats = 38016 B

#define BIGV 3.4e38f
#define BIGI 0x3fffffff

// plain strict-< insert: stable while indices ascend during the scan
__device__ __forceinline__ void top3_insert(float v, int s,
                                            float& d0, float& d1, float& d2,
                                            int& i0, int& i1, int& i2) {
    if (v < d2) {
        if (v < d1) {
            d2 = d1; i2 = i1;
            if (v < d0) { d1 = d0; i1 = i0; d0 = v; i0 = s; }
            else        { d1 = v;  i1 = s; }
        } else {
            d2 = v; i2 = s;
        }
    }
}

__device__ __forceinline__ bool lessvi(float v, int i, float w, int j) {
    return (v < w) || (v == w && i < j);
}

// lexicographic (value, index) insert for merges
__device__ __forceinline__ void top3_insert_vi(float v, int s,
                                               float& d0, float& d1, float& d2,
                                               int& i0, int& i1, int& i2) {
    if (lessvi(v, s, d2, i2)) {
        if (lessvi(v, s, d1, i1)) {
            d2 = d1; i2 = i1;
            if (lessvi(v, s, d0, i0)) { d1 = d0; i1 = i0; d0 = v; i0 = s; }
            else                      { d1 = v;  i1 = s; }
        } else {
            d2 = v; i2 = s;
        }
    }
}

// packed f32x2 add (Blackwell)
__device__ __forceinline__ void add2(float& rx, float& ry,
                                     float ax, float ay, float bx, float by) {
    uint64_t a, b, r;
    asm("mov.b64 %0, {%1, %2};" : "=l"(a) : "f"(ax), "f"(ay));
    asm("mov.b64 %0, {%1, %2};" : "=l"(b) : "f"(bx), "f"(by));
    asm("add.rn.f32x2 %0, %1, %2;" : "=l"(r) : "l"(a), "l"(b));
    asm("mov.b64 {%0, %1}, %2;" : "=f"(rx), "=f"(ry) : "l"(r));
}

__global__ __launch_bounds__(256, 5) void interp_kernel(
    const float* __restrict__ x,            // (B,NT, NL*S, NV, F)
    const void*  __restrict__ mask_raw,     // (B,NT, NL*S, NV) — dtype detected
    const float* __restrict__ dist,         // (B, NL, T, S)
    float* __restrict__ out)
{
    __shared__ float sm[SMEM_FLOATS];
    __shared__ int s_flags[2];

    const int bid   = blockIdx.x;
    const int tb    = bid & 1;               // which half of the 64 targets
    const int group = bid >> 1;
    const int l     = group & 255;
    const int nt    = (group >> 8) & 1;
    const int b     = group >> 9;
    const int tid   = threadIdx.x;

    if (tid == 0) { s_flags[0] = 0; s_flags[1] = 0; }
    __syncthreads();

    // ---- mask dtype detection from first 1024 bytes ----
    {
        const uchar4* mb = (const uchar4*)mask_raw;
        uchar4 q = mb[tid];
        int u8  = (q.y == 1) | (q.z == 1) | (q.w == 1);
        int f32 = (q.x == 0x3F) | (q.y == 0x3F) | (q.z == 0x3F) | (q.w == 0x3F);
        if (u8)  atomicOr(&s_flags[0], 1);
        if (f32) atomicOr(&s_flags[1], 1);
    }

    // ---- stage dist tile: 32 targets x 256 sources, coalesced float4 loads ----
    {
        const float4* dsrc = (const float4*)(
            dist + (((size_t)(b * NLG + l)) * TT + tb * 32) * SS);
        #pragma unroll
        for (int i = 0; i < 8; i++) {
            int g = tid + i * 256;            // float4 index within 32x256 tile
            float4 v = dsrc[g];
            int flat = g * 4;
            int t = flat >> 8;                // 0..31
            int s = flat & 255;
            int hh = s >> 7;
            int off = t * ROWST + hh * HROW + (s & 127);
            *(float4*)&sm[off] = v;
        }
    }
    __syncthreads();
    const int mkind = s_flags[0] ? 0 : (s_flags[1] ? 2 : 1);

    // ---- stage mask -> penalty table [nv][h][132] (tid = s) ----
    {
        const size_t moff = ((size_t)((b * NTT + nt) * NLG + l)) * SS * NVV;
        const int hh  = tid >> 7;
        const int sl  = tid & 127;
        float* pb = &sm[PEN_OFF + hh * HROW + sl];
        if (mkind == 0) {            // uint8
            const uchar4* msrc = (const uchar4*)((const unsigned char*)mask_raw + moff);
            uchar4 m = msrc[tid];
            pb[0 * ROWST] = m.x ? MASKVAL : 0.0f;
            pb[1 * ROWST] = m.y ? MASKVAL : 0.0f;
            pb[2 * ROWST] = m.z ? MASKVAL : 0.0f;
            pb[3 * ROWST] = m.w ? MASKVAL : 0.0f;
        } else if (mkind == 1) {     // int32
            const int4* msrc = (const int4*)((const int*)mask_raw + moff);
            int4 m = msrc[tid];
            pb[0 * ROWST] = m.x ? MASKVAL : 0.0f;
            pb[1 * ROWST] = m.y ? MASKVAL : 0.0f;
            pb[2 * ROWST] = m.z ? MASKVAL : 0.0f;
            pb[3 * ROWST] = m.w ? MASKVAL : 0.0f;
        } else {                     // float32 0/1
            const float4* msrc = (const float4*)((const float*)mask_raw + moff);
            float4 m = msrc[tid];
            pb[0 * ROWST] = m.x * MASKVAL;
            pb[1 * ROWST] = m.y * MASKVAL;
            pb[2 * ROWST] = m.z * MASKVAL;
            pb[3 * ROWST] = m.w * MASKVAL;
        }
    }
    __syncthreads();

    // thread decomposition: nv = tid&3, h = (tid>>2)&1 (s-half), t = tid>>3
    const int nv = tid & 3;
    const int h  = (tid >> 2) & 1;
    const int tl = tid >> 3;                  // local target 0..31
    const int t  = tl + tb * 32;              // global target 0..63

    const float* drow = &sm[tl * ROWST + h * HROW];
    const float* prow = &sm[PEN_OFF + nv * ROWST + h * HROW];
    const int sbase = h * 128;

    // 4 independent top-3 accumulators (partition p = s % 4)
    float a0 = BIGV, a1 = BIGV, a2 = BIGV;  int ai0 = BIGI, ai1 = BIGI, ai2 = BIGI;
    float b0 = BIGV, b1 = BIGV, b2 = BIGV;  int bi0 = BIGI, bi1 = BIGI, bi2 = BIGI;
    float c0 = BIGV, c1 = BIGV, c2 = BIGV;  int ci0 = BIGI, ci1 = BIGI, ci2 = BIGI;
    float e0 = BIGV, e1 = BIGV, e2 = BIGV;  int ei0 = BIGI, ei1 = BIGI, ei2 = BIGI;

    #pragma unroll 16
    for (int k = 0; k < 32; k++) {
        float4 dv = *(const float4*)(drow + k * 4);
        float4 pv = *(const float4*)(prow + k * 4);
        float vx, vy, vz, vw;
        add2(vx, vy, dv.x, dv.y, pv.x, pv.y);
        add2(vz, vw, dv.z, dv.w, pv.z, pv.w);
        int s = sbase + k * 4;
        top3_insert(vx, s + 0, a0, a1, a2, ai0, ai1, ai2);
        top3_insert(vy, s + 1, b0, b1, b2, bi0, bi1, bi2);
        top3_insert(vz, s + 2, c0, c1, c2, ci0, ci1, ci2);
        top3_insert(vw, s + 3, e0, e1, e2, ei0, ei1, ei2);
    }

    // merge partitions 1..3 into partition 0 (lexicographic)
    top3_insert_vi(b0, bi0, a0, a1, a2, ai0, ai1, ai2);
    top3_insert_vi(b1, bi1, a0, a1, a2, ai0, ai1, ai2);
    top3_insert_vi(b2, bi2, a0, a1, a2, ai0, ai1, ai2);
    top3_insert_vi(c0, ci0, a0, a1, a2, ai0, ai1, ai2);
    top3_insert_vi(c1, ci1, a0, a1, a2, ai0, ai1, ai2);
    top3_insert_vi(c2, ci2, a0, a1, a2, ai0, ai1, ai2);
    top3_insert_vi(e0, ei0, a0, a1, a2, ai0, ai1, ai2);
    top3_insert_vi(e1, ei1, a0, a1, a2, ai0, ai1, ai2);
    top3_insert_vi(e2, ei2, a0, a1, a2, ai0, ai1, ai2);

    // merge the two s-halves via shuffle (partner = lane ^ 4)
    {
        float ov0 = __shfl_xor_sync(0xffffffffu, a0, 4);
        float ov1 = __shfl_xor_sync(0xffffffffu, a1, 4);
        float ov2 = __shfl_xor_sync(0xffffffffu, a2, 4);
        int   oi0 = __shfl_xor_sync(0xffffffffu, ai0, 4);
        int   oi1 = __shfl_xor_sync(0xffffffffu, ai1, 4);
        int   oi2 = __shfl_xor_sync(0xffffffffu, ai2, 4);
        top3_insert_vi(ov0, oi0, a0, a1, a2, ai0, ai1, ai2);
        top3_insert_vi(ov1, oi1, a0, a1, a2, ai0, ai1, ai2);
        top3_insert_vi(ov2, oi2, a0, a1, a2, ai0, ai1, ai2);
    }

    // ---- weights ----
    float q0 = fmaxf(a0, CUTOFF);
    float q1 = fmaxf(a1, CUTOFF);
    float q2 = fmaxf(a2, CUTOFF);
    float w0 = 1.0f / (q0 * q0);
    float w1 = 1.0f / (q1 * q1);
    float w2 = 1.0f / (q2 * q2);
    float inv = 1.0f / (w0 + w1 + w2);
    w0 *= inv; w1 *= inv; w2 *= inv;

    // ---- gather + blend: each half-thread writes 2 of the 4 float4s ----
    const float* xb = x + ((size_t)((b * NTT + nt) * NLG + l)) * SS * NVV * FF;
    const float4* p0 = (const float4*)(xb + ((size_t)ai0 * NVV + nv) * FF);
    const float4* p1 = (const float4*)(xb + ((size_t)ai1 * NVV + nv) * FF);
    const float4* p2 = (const float4*)(xb + ((size_t)ai2 * NVV + nv) * FF);

    const size_t row = (size_t)((b * NTT + nt) * (NLG * TT)) + (size_t)l * TT + t;
    float4* op = (float4*)(out + (row * NVV + nv) * FF);

    const int j0 = h * 2;
    #pragma unroll
    for (int j = j0; j < j0 + 2; j++) {
        float4 va = p0[j], vb = p1[j], vc = p2[j];
        float4 r;
        r.x = w0 * va.x + w1 * vb.x + w2 * vc.x;
        r.y = w0 * va.y + w1 * vb.y + w2 * vc.y;
        r.z = w0 * va.z + w1 * vb.z + w2 * vc.z;
        r.w = w0 * va.w + w1 * vb.w + w2 * vc.w;
        op[j] = r;
    }

    // ---- dist_vals output: split between the two half-threads ----
    const size_t XSZ = (size_t)NB * NTT * NLG * TT * NVV * FF;  // 4,194,304
    size_t dbase = XSZ + (row * KNN) * NVV + nv;
    if (h == 0) {
        out[dbase]       = q0;
        out[dbase + NVV] = q1;
    } else {
        out[dbase + 2 * NVV] = q2;
    }
}

extern "C" void kernel_launch(void* const* d_in, const int* in_sizes, int n_in,
                              void* d_out, int out_size) {
    const float* x    = (const float*)d_in[0];
    const void*  mask = (const void*)d_in[1];
    const float* dist = (const float*)d_in[2];
    float*       out  = (float*)d_out;

    interp_kernel<<<NB * NTT * NLG * 2, 256>>>(x, mask, dist, out);
}

// round 7
// speedup vs baseline: 1.4207x; 1.1152x over previous
#include <cuda_runtime.h>
#include <cstdint>

#define NB    2
#define NTT   2
#define NLG   256
#define TT    64
#define SS    256
#define NVV   4
#define FF    16
#define KNN   3
#define CUTOFF   1e-3f
#define MASKVAL  1e6f

#define ROWST 264          // [t or nv][h(2)][132] layout, stride 264 floats
#define CAP   16           // pool capacity per (t, chunk)
#define PSTR  (8*CAP)      // pool stride per t = 128

#define BIGV 3.4e38f
#define BIGI 0x3fffffff

__device__ __forceinline__ bool lessvi(float v, int i, float w, int j) {
    return (v < w) || (v == w && i < j);
}

// exact lexicographic (value, index) top-3 insert
__device__ __forceinline__ void top3_insert_vi(float v, int s,
                                               float& d0, float& d1, float& d2,
                                               int& i0, int& i1, int& i2) {
    if (lessvi(v, s, d2, i2)) {
        if (lessvi(v, s, d1, i1)) {
            d2 = d1; i2 = i1;
            if (lessvi(v, s, d0, i0)) { d1 = d0; i1 = i0; d0 = v; i0 = s; }
            else                      { d1 = v;  i1 = s; }
        } else {
            d2 = v; i2 = s;
        }
    }
}

__device__ __forceinline__ int offmap(int s) {  // s -> padded layout offset
    return s + ((s >> 7) << 2);                 // s<128: s ; s>=128: s+4
}

__global__ __launch_bounds__(256, 5) void interp_kernel(
    const float* __restrict__ x,            // (B,NT, NL*S, NV, F)
    const void*  __restrict__ mask_raw,     // (B,NT, NL*S, NV) — dtype detected
    const float* __restrict__ dist,         // (B, NL, T, S)
    float* __restrict__ out)
{
    __shared__ float sdist[32 * ROWST];                  // 33.8 KB
    __shared__ float spen [NVV * ROWST];                 // 4.2 KB
    __shared__ unsigned char pool[32 * PSTR];            // 4 KB
    __shared__ unsigned char cnts[32 * 8];               // 256 B
    __shared__ int s_flags[2];

    const int bid   = blockIdx.x;
    const int tb    = bid & 1;               // half of the 64 targets
    const int group = bid >> 1;
    const int l     = group & 255;
    const int nt    = (group >> 8) & 1;
    const int b     = group >> 9;
    const int tid   = threadIdx.x;

    if (tid == 0) { s_flags[0] = 0; s_flags[1] = 0; }
    __syncthreads();

    // ---- mask dtype detection from first 1024 bytes ----
    {
        const uchar4* mb = (const uchar4*)mask_raw;
        uchar4 q = mb[tid];
        int u8  = (q.y == 1) | (q.z == 1) | (q.w == 1);
        int f32 = (q.x == 0x3F) | (q.y == 0x3F) | (q.z == 0x3F) | (q.w == 0x3F);
        if (u8)  atomicOr(&s_flags[0], 1);
        if (f32) atomicOr(&s_flags[1], 1);
    }

    // ---- stage dist tile (32 targets x 256 sources), coalesced ----
    {
        const float4* dsrc = (const float4*)(
            dist + (((size_t)(b * NLG + l)) * TT + tb * 32) * SS);
        #pragma unroll
        for (int i = 0; i < 8; i++) {
            int g = tid + i * 256;
            float4 v = dsrc[g];
            int flat = g * 4;
            int t = flat >> 8;
            int s = flat & 255;
            *(float4*)&sdist[t * ROWST + offmap(s)] = v;
        }
    }
    __syncthreads();
    const int mkind = s_flags[0] ? 0 : (s_flags[1] ? 2 : 1);

    // ---- stage mask -> penalty table [nv][...] (tid = s) ----
    {
        const size_t moff = ((size_t)((b * NTT + nt) * NLG + l)) * SS * NVV;
        float* pb = &spen[offmap(tid)];
        if (mkind == 0) {            // uint8
            const uchar4* msrc = (const uchar4*)((const unsigned char*)mask_raw + moff);
            uchar4 m = msrc[tid];
            pb[0 * ROWST] = m.x ? MASKVAL : 0.0f;
            pb[1 * ROWST] = m.y ? MASKVAL : 0.0f;
            pb[2 * ROWST] = m.z ? MASKVAL : 0.0f;
            pb[3 * ROWST] = m.w ? MASKVAL : 0.0f;
        } else if (mkind == 1) {     // int32
            const int4* msrc = (const int4*)((const int*)mask_raw + moff);
            int4 m = msrc[tid];
            pb[0 * ROWST] = m.x ? MASKVAL : 0.0f;
            pb[1 * ROWST] = m.y ? MASKVAL : 0.0f;
            pb[2 * ROWST] = m.z ? MASKVAL : 0.0f;
            pb[3 * ROWST] = m.w ? MASKVAL : 0.0f;
        } else {                     // float32 0/1
            const float4* msrc = (const float4*)((const float*)mask_raw + moff);
            float4 m = msrc[tid];
            pb[0 * ROWST] = m.x * MASKVAL;
            pb[1 * ROWST] = m.y * MASKVAL;
            pb[2 * ROWST] = m.z * MASKVAL;
            pb[3 * ROWST] = m.w * MASKVAL;
        }
    }
    __syncthreads();

    // ================= Phase A: threshold + compaction =================
    // lane = (t: tid>>3, chunk: tid&7); chunk c handles s = c + 8j (interleaved)
    const int at = tid >> 3;
    const int ac = tid & 7;
    const float* dbt = &sdist[at * ROWST];

    float m = BIGV;
    #pragma unroll
    for (int j = 0; j < 16; j++)  m = fminf(m, dbt[ac + 8 * j]);        // s < 128
    #pragma unroll
    for (int j = 16; j < 32; j++) m = fminf(m, dbt[ac + 8 * j + 4]);    // s >= 128

    float tau = m;
    tau = fmaxf(tau, __shfl_xor_sync(0xffffffffu, tau, 1));
    tau = fmaxf(tau, __shfl_xor_sync(0xffffffffu, tau, 2));
    tau = fmaxf(tau, __shfl_xor_sync(0xffffffffu, tau, 4));
    // all 8 chunk-lanes of this t now hold tau(t); >=8 elements are <= tau.

    {
        unsigned char* mypool = &pool[at * PSTR + ac * CAP];
        int cnt = 0;
        #pragma unroll
        for (int j = 0; j < 16; j++) {
            int s = ac + 8 * j;
            float v = dbt[s];
            if (v <= tau) { if (cnt < CAP) mypool[cnt] = (unsigned char)s; cnt++; }
        }
        #pragma unroll
        for (int j = 16; j < 32; j++) {
            int s = ac + 8 * j;
            float v = dbt[s + 4];
            if (v <= tau) { if (cnt < CAP) mypool[cnt] = (unsigned char)s; cnt++; }
        }
        cnts[at * 8 + ac] = (unsigned char)cnt;
    }
    __syncthreads();

    // ================= Phase B: exact top-3 over the pool =================
    const int nv = tid & 3;
    const int ph = (tid >> 2) & 1;
    const int t  = tid >> 3;                 // == at, so tau is for this t
    const float* dt = &sdist[t * ROWST];
    const float* pn = &spen[nv * ROWST];

    float a0 = BIGV, a1 = BIGV, a2 = BIGV;
    int   ai0 = BIGI, ai1 = BIGI, ai2 = BIGI;
    int ovf = 0;

    #pragma unroll
    for (int c = 0; c < 8; c++) {
        int n = cnts[t * 8 + c];
        if (n > CAP) { ovf = 1; n = CAP; }
        const unsigned char* pp = &pool[t * PSTR + c * CAP];
        for (int i = ph; i < n; i += 2) {
            int s = pp[i];
            int off = offmap(s);
            float v = dt[off] + pn[off];
            top3_insert_vi(v, s, a0, a1, a2, ai0, ai1, ai2);
        }
    }

    // merge the two ph lanes (partner = lane ^ 4) — all shfls unconditional
    {
        float ov0 = __shfl_xor_sync(0xffffffffu, a0, 4);
        float ov1 = __shfl_xor_sync(0xffffffffu, a1, 4);
        float ov2 = __shfl_xor_sync(0xffffffffu, a2, 4);
        int   oi0 = __shfl_xor_sync(0xffffffffu, ai0, 4);
        int   oi1 = __shfl_xor_sync(0xffffffffu, ai1, 4);
        int   oi2 = __shfl_xor_sync(0xffffffffu, ai2, 4);
        top3_insert_vi(ov0, oi0, a0, a1, a2, ai0, ai1, ai2);
        top3_insert_vi(ov1, oi1, a0, a1, a2, ai0, ai1, ai2);
        top3_insert_vi(ov2, oi2, a0, a1, a2, ai0, ai1, ai2);
    }
    // NOTE: shfl must NOT be inside a short-circuit (caused R6 deadlock)
    int ovf_other = __shfl_xor_sync(0xffffffffu, ovf, 4);
    int ovf2 = ovf | ovf_other;

    // safety: excluded sources have dist > tau, so a2 <= tau proves exactness
    bool flag = (ovf2 != 0) || (a2 > tau);
    if (__any_sync(0xffffffffu, flag)) {
        // rare exact fallback: full 256-candidate rescan, whole warp participates
        float f0 = BIGV, f1 = BIGV, f2 = BIGV;
        int   g0 = BIGI, g1 = BIGI, g2 = BIGI;
        for (int k = 0; k < 128; k++) {
            int s = (k << 1) | ph;
            int off = offmap(s);
            float v = dt[off] + pn[off];
            top3_insert_vi(v, s, f0, f1, f2, g0, g1, g2);
        }
        float ov0 = __shfl_xor_sync(0xffffffffu, f0, 4);
        float ov1 = __shfl_xor_sync(0xffffffffu, f1, 4);
        float ov2 = __shfl_xor_sync(0xffffffffu, f2, 4);
        int   oi0 = __shfl_xor_sync(0xffffffffu, g0, 4);
        int   oi1 = __shfl_xor_sync(0xffffffffu, g1, 4);
        int   oi2 = __shfl_xor_sync(0xffffffffu, g2, 4);
        top3_insert_vi(ov0, oi0, f0, f1, f2, g0, g1, g2);
        top3_insert_vi(ov1, oi1, f0, f1, f2, g0, g1, g2);
        top3_insert_vi(ov2, oi2, f0, f1, f2, g0, g1, g2);
        if (flag) {
            a0 = f0; a1 = f1; a2 = f2;
            ai0 = g0; ai1 = g1; ai2 = g2;
        }
    }

    // ---- weights ----
    float q0 = fmaxf(a0, CUTOFF);
    float q1 = fmaxf(a1, CUTOFF);
    float q2 = fmaxf(a2, CUTOFF);
    float w0 = 1.0f / (q0 * q0);
    float w1 = 1.0f / (q1 * q1);
    float w2 = 1.0f / (q2 * q2);
    float inv = 1.0f / (w0 + w1 + w2);
    w0 *= inv; w1 *= inv; w2 *= inv;

    // ---- gather + blend: each ph lane writes 2 of the 4 float4s ----
    const int tg = t + tb * 32;              // global target 0..63
    const float* xb = x + ((size_t)((b * NTT + nt) * NLG + l)) * SS * NVV * FF;
    const float4* p0 = (const float4*)(xb + ((size_t)ai0 * NVV + nv) * FF);
    const float4* p1 = (const float4*)(xb + ((size_t)ai1 * NVV + nv) * FF);
    const float4* p2 = (const float4*)(xb + ((size_t)ai2 * NVV + nv) * FF);

    const size_t row = (size_t)((b * NTT + nt) * (NLG * TT)) + (size_t)l * TT + tg;
    float4* op = (float4*)(out + (row * NVV + nv) * FF);

    const int j0 = ph * 2;
    #pragma unroll
    for (int j = j0; j < j0 + 2; j++) {
        float4 va = p0[j], vb = p1[j], vc = p2[j];
        float4 r;
        r.x = w0 * va.x + w1 * vb.x + w2 * vc.x;
        r.y = w0 * va.y + w1 * vb.y + w2 * vc.y;
        r.z = w0 * va.z + w1 * vb.z + w2 * vc.z;
        r.w = w0 * va.w + w1 * vb.w + w2 * vc.w;
        op[j] = r;
    }

    // ---- dist_vals output: split between the two ph lanes ----
    const size_t XSZ = (size_t)NB * NTT * NLG * TT * NVV * FF;  // 4,194,304
    size_t dbase = XSZ + (row * KNN) * NVV + nv;
    if (ph == 0) {
        out[dbase]       = q0;
        out[dbase + NVV] = q1;
    } else {
        out[dbase + 2 * NVV] = q2;
    }
}

extern "C" void kernel_launch(void* const* d_in, const int* in_sizes, int n_in,
                              void* d_out, int out_size) {
    const float* x    = (const float*)d_in[0];
    const void*  mask = (const void*)d_in[1];
    const float* dist = (const float*)d_in[2];
    float*       out  = (float*)d_out;

    interp_kernel<<<NB * NTT * NLG * 2, 256>>>(x, mask, dist, out);
}